// round 3
// baseline (speedup 1.0000x reference)
#include <cuda_runtime.h>
#include <math.h>

// Problem constants (fixed by the dataset)
#define N_   8192
#define C_   19
#define M_   10
#define CM_  190          // C_*M_
#define K_   64
#define NT   8            // n-rows per block
#define TPB  192          // threads per block (>= CM_)
#define PVN  (C_*M_*K_)   // 12160

__device__ int d_flag;    // 1 => proto_var uniform (fast path valid)

// ---- packed f32x2 helpers (Blackwell FFMA2) --------------------------------
__device__ __forceinline__ unsigned long long
fma2(unsigned long long a, unsigned long long b, unsigned long long c) {
    unsigned long long d;
    asm("fma.rn.f32x2 %0, %1, %2, %3;" : "=l"(d) : "l"(a), "l"(b), "l"(c));
    return d;
}
__device__ __forceinline__ unsigned long long d2u(double v) {
    return __double_as_longlong(v);
}

// ---- kernel 1: uniformity check --------------------------------------------
__global__ void check_kernel(const float* __restrict__ pv) {
    const float v0 = pv[0];
    int ok = 1;
    #pragma unroll 4
    for (int i = threadIdx.x; i < PVN; i += 1024)
        ok &= (pv[i] == v0);
    const int all = __syncthreads_and(ok);
    if (threadIdx.x == 0) d_flag = all;
}

// ---- kernel 2: fused precompute + mainloop (+ general fallback branch) -----
__global__ void __launch_bounds__(TPB, 4)
main_kernel(const float* __restrict__ x,  const float* __restrict__ xv,
            const float* __restrict__ p,  const float* __restrict__ pv,
            float* __restrict__ out) {
    __shared__ __align__(16) float rs[NT * K_];   // 1/(xv+v0)        2 KB
    __shared__ __align__(16) float as[NT * K_];   // -2*x/(xv+v0)     2 KB
    __shared__ float base_s[NT];

    const int t  = threadIdx.x;
    const int n0 = blockIdx.x * NT;

    if (d_flag) {
        // ================= FAST PATH (uniform proto_var) =================
        const float v0 = __ldg(pv);

        if (t < NT) base_s[t] = 0.0f;
        __syncthreads();

        // --- block-local precompute: 8 rows x 64 k = 512 elements -------
        // Each warp covers a 32-aligned half-row per iteration, so a
        // full-warp shuffle reduce is segment-exact.
        #pragma unroll
        for (int it = 0; it < 3; ++it) {
            const int idx = t + it * TPB;
            const bool active = (idx < NT * K_);
            float tval = 0.0f;
            int row = 0;
            if (active) {
                row = idx >> 6;
                const int g = (n0 + row) * K_ + (idx & 63);
                const float xx = x[g];
                const float s  = xv[g] + v0;
                const float r  = 1.0f / s;
                rs[idx] = r;
                as[idx] = -2.0f * xx * r;
                tval = xx * xx * r + logf(s);
            }
            #pragma unroll
            for (int off = 16; off; off >>= 1)
                tval += __shfl_down_sync(0xffffffffu, tval, off);
            if (active && (t & 31) == 0) atomicAdd(&base_s[row], tval);
        }
        __syncthreads();

        // --- mainloop: acc += p * (p*r + a2) over k, per (j, cm) ---------
        const int cm = (t < CM_) ? t : 0;

        unsigned long long acc[NT];
        #pragma unroll
        for (int j = 0; j < NT; ++j) acc[j] = 0ull;

        #pragma unroll
        for (int chunk = 0; chunk < 4; ++chunk) {
            // prototype k-chunk (16 floats = 8 packed pairs) from L1
            unsigned long long pk[8];
            const double2* prow =
                reinterpret_cast<const double2*>(p + cm * K_ + chunk * 16);
            #pragma unroll
            for (int q = 0; q < 4; ++q) {
                const double2 v = __ldg(prow + q);
                pk[2*q]   = d2u(v.x);
                pk[2*q+1] = d2u(v.y);
            }

            #pragma unroll
            for (int j = 0; j < NT; ++j) {
                unsigned long long a = acc[j];
                const double2* r2 =
                    reinterpret_cast<const double2*>(rs + j * K_ + chunk * 16);
                const double2* a2 =
                    reinterpret_cast<const double2*>(as + j * K_ + chunk * 16);
                #pragma unroll
                for (int q = 0; q < 4; ++q) {
                    const double2 rv = r2[q];
                    const double2 av = a2[q];
                    unsigned long long t0 = fma2(pk[2*q],   d2u(rv.x), d2u(av.x));
                    a = fma2(pk[2*q],   t0, a);
                    unsigned long long t1 = fma2(pk[2*q+1], d2u(rv.y), d2u(av.y));
                    a = fma2(pk[2*q+1], t1, a);
                }
                acc[j] = a;
            }
        }

        if (t < CM_) {
            #pragma unroll
            for (int j = 0; j < NT; ++j) {
                const double ad = __longlong_as_double(acc[j]);
                const float2 f2 = *reinterpret_cast<const float2*>(&ad);
                out[(n0 + j) * CM_ + cm] =
                    -0.0078125f * (f2.x + f2.y + base_s[j]);  // -0.5/64
            }
        }
    } else {
        // ================= GENERAL FALLBACK (non-uniform pv) ============
        for (int idx = t; idx < NT * CM_; idx += TPB) {
            const int j  = idx / CM_;
            const int cm = idx % CM_;
            const int n  = n0 + j;
            float acc = 0.0f;
            for (int k = 0; k < K_; ++k) {
                const float s = xv[n * K_ + k] + pv[cm * K_ + k];
                const float d = p[cm * K_ + k] - x[n * K_ + k];
                acc += d * d / s + logf(s);
            }
            out[n * CM_ + cm] = -0.5f * acc * (1.0f / (float)K_);
        }
    }
}

// ---- launch -----------------------------------------------------------------
extern "C" void kernel_launch(void* const* d_in, const int* in_sizes, int n_in,
                              void* d_out, int out_size) {
    const float* x  = (const float*)d_in[0];   // [8192,64]
    const float* xv = (const float*)d_in[1];   // [8192,64]
    const float* p  = (const float*)d_in[2];   // [19,10,64]
    const float* pv = (const float*)d_in[3];   // [19,10,64]
    float* out = (float*)d_out;                // [8192,19,10]

    check_kernel<<<1, 1024>>>(pv);
    main_kernel<<<N_ / NT, TPB>>>(x, xv, p, pv, out);
}

// round 4
// speedup vs baseline: 1.2554x; 1.2554x over previous
#include <cuda_runtime.h>
#include <math.h>

// Problem constants (fixed by the dataset)
#define N_   8192
#define C_   19
#define M_   10
#define CM_  190          // C_*M_
#define K_   64
#define NT   16           // n-rows per block
#define TPB  192          // threads per block (>= CM_)
#define PVN  (C_*M_*K_)   // 12160

__device__ int d_flag;    // 1 => proto_var uniform (fast path valid)

// ---- packed f32x2 helpers (Blackwell FFMA2) --------------------------------
__device__ __forceinline__ unsigned long long
fma2(unsigned long long a, unsigned long long b, unsigned long long c) {
    unsigned long long d;
    asm("fma.rn.f32x2 %0, %1, %2, %3;" : "=l"(d) : "l"(a), "l"(b), "l"(c));
    return d;
}
__device__ __forceinline__ unsigned long long d2u(double v) {
    return __double_as_longlong(v);
}

// ---- kernel 1: uniformity check --------------------------------------------
__global__ void check_kernel(const float* __restrict__ pv) {
    const float v0 = pv[0];
    int ok = 1;
    #pragma unroll 4
    for (int i = threadIdx.x; i < PVN; i += 1024)
        ok &= (pv[i] == v0);
    const int all = __syncthreads_and(ok);
    if (threadIdx.x == 0) d_flag = all;
}

// ---- kernel 2: fused precompute + mainloop ----------------------------------
__global__ void __launch_bounds__(TPB, 4)
main_kernel(const float* __restrict__ x,  const float* __restrict__ xv,
            const float* __restrict__ p,  const float* __restrict__ pv,
            float* __restrict__ out) {
    // pT: transposed pair-packed prototypes for HALF of K at a time:
    //     pT[k2][cm] = (p[cm][2*k2], p[cm][2*k2+1]) as one 8-byte element.
    __shared__ double pT[16 * CM_];                 // 23.75 KB
    // ras4[j*32 + kp] = { r(2kp), r(2kp+1), a(2kp), a(2kp+1) } for full K
    __shared__ __align__(16) float4 ras4[NT * 32];  // 8 KB
    __shared__ float base_s[NT];

    const int t  = threadIdx.x;
    const int n0 = blockIdx.x * NT;

    if (d_flag) {
        // ================= FAST PATH (uniform proto_var) =================
        const float v0 = __ldg(pv);

        if (t < NT) base_s[t] = 0.0f;
        __syncthreads();

        // --- block-local precompute: 16 rows x 64 k = 1024 elements -----
        float* ras = reinterpret_cast<float*>(ras4);
        #pragma unroll
        for (int it = 0; it < 6; ++it) {
            const int idx = t + it * TPB;
            const bool active = (idx < NT * K_);
            float tval = 0.0f;
            int row = 0;
            if (active) {
                row = idx >> 6;
                const int k = idx & 63;
                const int g = (n0 + row) * K_ + k;
                const float xx = x[g];
                const float s  = xv[g] + v0;
                const float r  = 1.0f / s;
                const int b = (row * 32 + (k >> 1)) * 4 + (k & 1);
                ras[b]     = r;
                ras[b + 2] = -2.0f * xx * r;
                tval = xx * xx * r + logf(s);
            }
            #pragma unroll
            for (int off = 16; off; off >>= 1)
                tval += __shfl_down_sync(0xffffffffu, tval, off);
            if (active && (t & 31) == 0) atomicAdd(&base_s[row], tval);
        }

        const int cm = (t < CM_) ? t : 0;
        const double* pd = reinterpret_cast<const double*>(p);  // pair view

        unsigned long long acc[NT];
        #pragma unroll
        for (int j = 0; j < NT; ++j) acc[j] = 0ull;

        #pragma unroll
        for (int pass = 0; pass < 2; ++pass) {
            __syncthreads();   // protect pT reuse + (pass0) ras readiness
            // fill pT for k-pairs [pass*16, pass*16+16): 190*16 elements,
            // coalesced 8B gmem reads, transposed smem writes
            for (int idx = t; idx < CM_ * 16; idx += TPB) {
                const int rcm = idx >> 4;
                const int k2  = idx & 15;
                pT[k2 * CM_ + rcm] = pd[rcm * 32 + pass * 16 + k2];
            }
            __syncthreads();

            #pragma unroll
            for (int chunk = 0; chunk < 2; ++chunk) {
                // 8 proto pairs for this cm, conflict-free LDS.64
                unsigned long long pk[8];
                #pragma unroll
                for (int q = 0; q < 8; ++q)
                    pk[q] = d2u(pT[(chunk * 8 + q) * CM_ + cm]);

                const int kp0 = pass * 16 + chunk * 8;
                #pragma unroll
                for (int j = 0; j < NT; ++j) {
                    unsigned long long a = acc[j];
                    const float4* rr = ras4 + j * 32 + kp0;
                    #pragma unroll
                    for (int q = 0; q < 8; ++q) {
                        const float4 v = rr[q];
                        const unsigned long long rv =
                            d2u(*reinterpret_cast<const double*>(&v.x));
                        const unsigned long long av =
                            d2u(*reinterpret_cast<const double*>(&v.z));
                        const unsigned long long t0 = fma2(pk[q], rv, av);
                        a = fma2(pk[q], t0, a);
                    }
                    acc[j] = a;
                }
            }
        }

        if (t < CM_) {
            #pragma unroll
            for (int j = 0; j < NT; ++j) {
                const double ad = __longlong_as_double(acc[j]);
                const float2 f2 = *reinterpret_cast<const float2*>(&ad);
                out[(n0 + j) * CM_ + cm] =
                    -0.0078125f * (f2.x + f2.y + base_s[j]);  // -0.5/64
            }
        }
    } else {
        // ================= GENERAL FALLBACK (non-uniform pv) ============
        for (int idx = t; idx < NT * CM_; idx += TPB) {
            const int j  = idx / CM_;
            const int cm = idx % CM_;
            const int n  = n0 + j;
            float acc = 0.0f;
            for (int k = 0; k < K_; ++k) {
                const float s = xv[n * K_ + k] + pv[cm * K_ + k];
                const float d = p[cm * K_ + k] - x[n * K_ + k];
                acc += d * d / s + logf(s);
            }
            out[n * CM_ + cm] = -0.5f * acc * (1.0f / (float)K_);
        }
    }
}

// ---- launch -----------------------------------------------------------------
extern "C" void kernel_launch(void* const* d_in, const int* in_sizes, int n_in,
                              void* d_out, int out_size) {
    const float* x  = (const float*)d_in[0];   // [8192,64]
    const float* xv = (const float*)d_in[1];   // [8192,64]
    const float* p  = (const float*)d_in[2];   // [19,10,64]
    const float* pv = (const float*)d_in[3];   // [19,10,64]
    float* out = (float*)d_out;                // [8192,19,10]

    check_kernel<<<1, 1024>>>(pv);
    main_kernel<<<N_ / NT, TPB>>>(x, xv, p, pv, out);
}